// round 14
// baseline (speedup 1.0000x reference)
#include <cuda_runtime.h>
#include <cuda_bf16.h>
#include <math.h>
#include <stdint.h>

#define Bb   2
#define Ls   4096
#define BLr  (Bb*Ls)          // 8192 rows
#define BNc  384
#define DIc  768
#define NSc  16
#define DCc  4
#define Rc   24
#define XDc  (Rc + 2*NSc)     // 56

#define NCH  16
#define CTs  (Ls/NCH)         // 256
#define TS1  64
#define TS3  32
#define DNs  (DIc*NSc)        // 12288

typedef __nv_bfloat16 bf16;

// ---------------- scratch (static device arrays; no allocation) -------------
__device__ float g_xz  [2][BLr*2*DIc];
__device__ float g_xdbl[2][BLr*XDc];
__device__ float g_dt  [2][BLr*DIc];
__device__ float g_do  [2][BLr*BNc];
__device__ float g_aprod[4*NCH*DNs];
__device__ float g_hendl[4*NCH*DNs];
__device__ float g_hin  [4*NCH*DNs];

// bf16 hi/lo activation operands
__device__ bf16 g_xhi[BLr*DIc],  g_xlo[BLr*DIc];
__device__ bf16 g_hhi[BLr*BNc],  g_hlo[BLr*BNc];
__device__ bf16 g_uhi[2][BLr*DIc], g_ulo[2][BLr*DIc];
__device__ bf16 g_yhi[2][BLr*DIc], g_ylo[2][BLr*DIc];
__device__ bf16 g_chi[BLr*BNc],  g_clo[BLr*BNc];

// transposed bf16 hi/lo weights [N,K]
__device__ bf16 g_wdhi[BNc*DIc],      g_wdlo[BNc*DIc];
__device__ bf16 g_wihi[2][2*DIc*BNc], g_wilo[2][2*DIc*BNc];
__device__ bf16 g_wxhi[2][XDc*DIc],   g_wxlo[2][XDc*DIc];
__device__ bf16 g_wohi[2][BNc*DIc],   g_wolo[2][BNc*DIc];
__device__ bf16 g_wuhi[DIc*BNc],      g_wulo[DIc*BNc];

// ---------------- helpers ------------------------------------------------------
__device__ __forceinline__ void split_bf16(float x, bf16& h, bf16& l){
    h = __float2bfloat16_rn(x);
    l = __float2bfloat16_rn(x - __bfloat162float(h));
}
__device__ __forceinline__ void mma16n8k16(float* d, const uint32_t* a, const uint32_t* b){
    asm volatile(
        "mma.sync.aligned.m16n8k16.row.col.f32.bf16.bf16.f32 "
        "{%0,%1,%2,%3}, {%4,%5,%6,%7}, {%8,%9}, {%0,%1,%2,%3};"
        : "+f"(d[0]), "+f"(d[1]), "+f"(d[2]), "+f"(d[3])
        : "r"(a[0]), "r"(a[1]), "r"(a[2]), "r"(a[3]), "r"(b[0]), "r"(b[1]));
}
__device__ __forceinline__ void ldsm4(uint32_t* r, uint32_t addr){
    asm volatile("ldmatrix.sync.aligned.m8n8.x4.shared.b16 {%0,%1,%2,%3}, [%4];"
        : "=r"(r[0]), "=r"(r[1]), "=r"(r[2]), "=r"(r[3]) : "r"(addr));
}
__device__ __forceinline__ void cp16(uint32_t dst, const void* src, int sz){
    asm volatile("cp.async.cg.shared.global [%0], [%1], 16, %2;\n"
                 :: "r"(dst), "l"(src), "r"(sz) : "memory");
}
#define CP_COMMIT() asm volatile("cp.async.commit_group;\n" ::: "memory")
#define CP_WAIT(n)  asm volatile("cp.async.wait_group %0;\n" :: "n"(n) : "memory")

// ---------------- bf16 GEMM, 128x128 tile, KT=32, 3-stage cp.async + LDSM ----
// Mainloop is TERM-MAJOR: all hh MMAs, then hl, then lh -> accumulator reuse
// distance of 16 MMAs (no back-to-back RAW on acc).
#define STAGE_U 10240
#define GEMM_SMEM (3*STAGE_U*4)   // 122880 bytes

__global__ __launch_bounds__(256, 1) void tc_gemm(
    const bf16* __restrict__ Ahi, const bf16* __restrict__ Alo, long sA,
    const bf16* __restrict__ Whi0, const bf16* __restrict__ Wlo0,
    const bf16* __restrict__ Whi1, const bf16* __restrict__ Wlo1,
    const float* __restrict__ bias,
    float* __restrict__ Cf, bf16* __restrict__ Chi, bf16* __restrict__ Clo, long sC,
    int N, int K, int revz)
{
    extern __shared__ uint32_t sm[];
    const uint32_t smb = (uint32_t)__cvta_generic_to_shared(sm);

    const int z = blockIdx.z;
    const bf16* __restrict__ Whi = z ? Whi1 : Whi0;
    const bf16* __restrict__ Wlo = z ? Wlo1 : Wlo0;
    Ahi += (long)z * sA;  Alo += (long)z * sA;
    if (Cf)  Cf  += (long)z * sC;
    if (Chi) { Chi += (long)z * sC; Clo += (long)z * sC; }

    const int tid  = threadIdx.x;
    const int lane = tid & 31;
    const int wid  = tid >> 5;
    const int warpM = wid & 3;
    const int warpN = wid >> 2;
    const int gid = lane >> 2;
    const int tig = lane & 3;

    const int crow = blockIdx.y * 128;
    const int ccol = blockIdx.x * 128;

    const uint32_t aOff = (uint32_t)((warpM * 32 + (lane & 15)) * 80 + (lane >> 4) * 16);
    const uint32_t bOff = (uint32_t)((warpN * 64 + (lane & 7) + ((lane >> 4) << 3)) * 80
                                     + ((lane >> 3) & 1) * 16);

    const bf16* srcA[4]; const bf16* srcB[4];
    uint32_t dA[4], dB[4]; int szB[4];
#pragma unroll
    for (int j = 0; j < 4; j++) {
        const int idx = tid + j * 256;
        const int part = idx >> 9;
        const int row  = (idx >> 2) & 127;
        const int seg  = idx & 3;
        int gRow = crow + row;
        if (revz && z == 1) {
            int bb = gRow / Ls, t = gRow - bb * Ls;
            gRow = bb * Ls + (Ls - 1 - t);
        }
        srcA[j] = (part ? Alo : Ahi) + (long)gRow * K + seg * 8;
        dA[j] = smb + (uint32_t)(part * 2560 + row * 20 + seg * 4) * 4u;
        const int ng = ccol + row;
        srcB[j] = (part ? Wlo : Whi) + (long)ng * K + seg * 8;
        szB[j] = (ng < N) ? 16 : 0;
        dB[j] = smb + (uint32_t)(5120 + part * 2560 + row * 20 + seg * 4) * 4u;
    }

#define ISSUE(KT, S)                                                           \
    {                                                                          \
        const uint32_t so = (uint32_t)(S) * STAGE_U * 4u;                      \
        const int ko = (KT) * 32;                                              \
        _Pragma("unroll")                                                      \
        for (int j = 0; j < 4; j++) cp16(dA[j] + so, srcA[j] + ko, 16);        \
        _Pragma("unroll")                                                      \
        for (int j = 0; j < 4; j++) cp16(dB[j] + so, srcB[j] + ko, szB[j]);    \
        CP_COMMIT();                                                           \
    }

    float acc[2][8][4];
#pragma unroll
    for (int m = 0; m < 2; m++)
#pragma unroll
        for (int n = 0; n < 8; n++)
#pragma unroll
            for (int q = 0; q < 4; q++) acc[m][n][q] = 0.f;

    const int nkt = K >> 5;

    ISSUE(0, 0);
    if (nkt > 1) ISSUE(1, 1);

    int s = 0;
    for (int kt = 0; kt < nkt; kt++) {
        if (kt + 1 < nkt) { CP_WAIT(1); }
        else              { CP_WAIT(0); }
        __syncthreads();

        const uint32_t stg = smb + (uint32_t)s * STAGE_U * 4u;
        const uint32_t aHi = stg + aOff;
        const uint32_t aLo = aHi + 2560u * 4u;
        const uint32_t bHi = stg + 5120u * 4u + bOff;
        const uint32_t bLo = bHi + 2560u * 4u;

#pragma unroll
        for (int ks = 0; ks < 2; ks++) {
            const uint32_t ko = (uint32_t)ks * 32u;
            uint32_t ah[2][4], al[2][4];
            uint32_t bh[4][4], bl[4][4];     // [g2] covers n = 2*g2, 2*g2+1
#pragma unroll
            for (int m = 0; m < 2; m++) {
                ldsm4(ah[m], aHi + m * 1280u + ko);
                ldsm4(al[m], aLo + m * 1280u + ko);
            }
#pragma unroll
            for (int g2 = 0; g2 < 4; g2++) {
                ldsm4(bh[g2], bHi + g2 * 1280u + ko);
                ldsm4(bl[g2], bLo + g2 * 1280u + ko);
            }
            // term 1: A_hi * B_hi  (16 independent accumulators)
#pragma unroll
            for (int g2 = 0; g2 < 4; g2++)
#pragma unroll
                for (int sub = 0; sub < 2; sub++)
#pragma unroll
                    for (int m = 0; m < 2; m++)
                        mma16n8k16(acc[m][g2*2+sub], ah[m], &bh[g2][sub*2]);
            // term 2: A_hi * B_lo
#pragma unroll
            for (int g2 = 0; g2 < 4; g2++)
#pragma unroll
                for (int sub = 0; sub < 2; sub++)
#pragma unroll
                    for (int m = 0; m < 2; m++)
                        mma16n8k16(acc[m][g2*2+sub], ah[m], &bl[g2][sub*2]);
            // term 3: A_lo * B_hi
#pragma unroll
            for (int g2 = 0; g2 < 4; g2++)
#pragma unroll
                for (int sub = 0; sub < 2; sub++)
#pragma unroll
                    for (int m = 0; m < 2; m++)
                        mma16n8k16(acc[m][g2*2+sub], al[m], &bh[g2][sub*2]);
        }

        if (kt + 2 < nkt) {
            const int s2 = (s + 2 >= 3) ? s - 1 : s + 2;
            ISSUE(kt + 2, s2);
        }
        s = (s + 1 == 3) ? 0 : s + 1;
    }

    // epilogue
#pragma unroll
    for (int m = 0; m < 2; m++) {
        const int r0 = crow + warpM * 32 + m * 16 + gid;
#pragma unroll
        for (int n = 0; n < 8; n++) {
            const int c = ccol + warpN * 64 + n * 8 + tig * 2;
            if (c < N) {
                float2 v0 = make_float2(acc[m][n][0], acc[m][n][1]);
                float2 v1 = make_float2(acc[m][n][2], acc[m][n][3]);
                if (bias) {
                    const float b0 = bias[c], b1 = bias[c + 1];
                    v0.x += b0; v0.y += b1; v1.x += b0; v1.y += b1;
                }
                if (Cf) {
                    *(float2*)&Cf[(long)r0 * N + c]       = v0;
                    *(float2*)&Cf[(long)(r0 + 8) * N + c] = v1;
                } else {
                    bf16 h0,l0,h1,l1;
                    split_bf16(v0.x, h0, l0); split_bf16(v0.y, h1, l1);
                    *(__nv_bfloat162*)&Chi[(long)r0 * N + c] = __nv_bfloat162(h0, h1);
                    *(__nv_bfloat162*)&Clo[(long)r0 * N + c] = __nv_bfloat162(l0, l1);
                    split_bf16(v1.x, h0, l0); split_bf16(v1.y, h1, l1);
                    *(__nv_bfloat162*)&Chi[(long)(r0 + 8) * N + c] = __nv_bfloat162(h0, h1);
                    *(__nv_bfloat162*)&Clo[(long)(r0 + 8) * N + c] = __nv_bfloat162(l0, l1);
                }
            }
        }
    }
#undef ISSUE
}

// ---------------- pre-split passes -------------------------------------------
__global__ void split_pass(const float* __restrict__ src, bf16* __restrict__ hi,
                           bf16* __restrict__ lo, long n)
{
    long i = (long)blockIdx.x * blockDim.x + threadIdx.x;
    if (i >= n) return;
    bf16 h, l; split_bf16(src[i], h, l);
    hi[i] = h; lo[i] = l;
}

struct SplitJobs {
    const float* src[8];
    bf16* hi[8];
    bf16* lo[8];
    int K[8];
    int N[8];
};
__global__ void wsplit_all(SplitJobs J)
{
    const int j = blockIdx.y;
    const int K = J.K[j], N = J.N[j];
    long i = (long)blockIdx.x * blockDim.x + threadIdx.x;
    if (i >= (long)N * K) return;
    int n = (int)(i / K), k = (int)(i % K);
    bf16 h, l; split_bf16(J.src[j][(long)k * N + n], h, l);
    J.hi[j][i] = h; J.lo[j][i] = l;
}

// ---------------- causal depthwise conv (DC=4) + SiLU -> bf16 hi/lo ----------
__global__ void conv_silu(const float* __restrict__ cw0, const float* __restrict__ cb0,
                          const float* __restrict__ cw1, const float* __restrict__ cb1)
{
    const int dir = blockIdx.y;
    long idx = (long)blockIdx.x * blockDim.x + threadIdx.x;
    if (idx >= (long)BLr * DIc) return;
    const int d = (int)(idx % DIc);
    const long row = idx / DIc;
    const int t = (int)(row % Ls);
    const float* cw = dir ? cw1 : cw0;
    const float* cb = dir ? cb1 : cb0;
    const float* xs = g_xz[dir];

    float s = cb[d];
#pragma unroll
    for (int k = 0; k < DCc; k++) {
        int tt = t - (DCc - 1) + k;
        if (tt >= 0) s += xs[(row - t + tt) * (2 * DIc) + d] * cw[d * DCc + k];
    }
    float sig = 1.f / (1.f + __expf(-s));
    float v = s * sig;
    bf16 h, l; split_bf16(v, h, l);
    g_uhi[dir][idx] = h; g_ulo[dir][idx] = l;
}

// ---------------- dt = softplus(dt_raw @ dt_W + dt_b) ------------------------
__global__ __launch_bounds__(256) void dt_kernel(
    const float* __restrict__ W0, const float* __restrict__ b0,
    const float* __restrict__ W1, const float* __restrict__ b1)
{
    const int dir = blockIdx.y;
    const int row0 = blockIdx.x * 16;
    const int tid = threadIdx.x;
    __shared__ float xd[16][Rc];
    for (int i = tid; i < 16 * Rc; i += 256) {
        int r = i / Rc, c = i - r * Rc;
        xd[r][c] = g_xdbl[dir][(long)(row0 + r) * XDc + c];
    }
    __syncthreads();
    const float* W  = dir ? W1 : W0;
    const float* bb = dir ? b1 : b0;
    for (int d = tid; d < DIc; d += 256) {
        float w[Rc];
#pragma unroll
        for (int r = 0; r < Rc; r++) w[r] = W[r * DIc + d];
        const float bias = bb[d];
#pragma unroll 4
        for (int rr = 0; rr < 16; rr++) {
            float s = bias;
#pragma unroll
            for (int r = 0; r < Rc; r++) s += xd[rr][r] * w[r];
            float sp = fmaxf(s, 0.f) + log1pf(__expf(-fabsf(s)));
            g_dt[dir][(long)(row0 + rr) * DIc + d] = sp;
        }
    }
}

// ---------------- chunked selective scan --------------------------------------
__global__ __launch_bounds__(256) void scan_p1(
    const float* __restrict__ Alog0, const float* __restrict__ Alog1)
{
    const int dir = blockIdx.z >> 1, b = blockIdx.z & 1;
    const int chunk = blockIdx.y;
    const int d0 = blockIdx.x * 16;
    const int tid = threadIdx.x, n = tid & 15, dd = tid >> 4;
    const float* Alog = dir ? Alog1 : Alog0;
    const float Ac = -expf(Alog[(d0 + dd) * NSc + n]);

    const long row0 = (long)b * Ls + (long)chunk * CTs;
    const float* dt_p = g_dt[dir]   + row0 * DIc + d0;
    const bf16*  uh_p = g_uhi[dir]  + row0 * DIc + d0;
    const bf16*  ul_p = g_ulo[dir]  + row0 * DIc + d0;
    const float* xd_p = g_xdbl[dir] + row0 * XDc;

    __shared__ float s_dt[2][TS1][16], s_u[2][TS1][16], s_B[2][TS1][16];

    float r0[4], r1[4], r2[4];
#define P1_LDG(SEG)                                                            \
    {                                                                          \
        _Pragma("unroll")                                                      \
        for (int j = 0; j < 4; j++) {                                          \
            const int ix = tid + j * 256;                                      \
            const int t = ix >> 4, c = ix & 15;                                \
            const long tt = (long)((SEG) * TS1 + t);                           \
            r0[j] = dt_p[tt * DIc + c];                                        \
            r1[j] = __bfloat162float(uh_p[tt * DIc + c])                       \
                  + __bfloat162float(ul_p[tt * DIc + c]);                      \
            r2[j] = xd_p[tt * XDc + Rc + c];                                   \
        }                                                                      \
    }
#define P1_STS(BUF)                                                            \
    {                                                                          \
        _Pragma("unroll")                                                      \
        for (int j = 0; j < 4; j++) {                                          \
            const int ix = tid + j * 256;                                      \
            const int t = ix >> 4, c = ix & 15;                                \
            s_dt[BUF][t][c] = r0[j];                                           \
            s_u [BUF][t][c] = r1[j];                                           \
            s_B [BUF][t][c] = r2[j];                                           \
        }                                                                      \
    }

    P1_LDG(0); P1_STS(0); __syncthreads();

    float h = 0.f, ap = 1.f;
    for (int seg = 0; seg < CTs / TS1; seg++) {
        const int buf = seg & 1;
        const bool more = (seg + 1) < (CTs / TS1);
        if (more) P1_LDG(seg + 1);
#pragma unroll 8
        for (int t = 0; t < TS1; t++) {
            const float dtv = s_dt[buf][t][dd];
            const float uv  = s_u [buf][t][dd];
            const float Bv  = s_B [buf][t][n];
            const float dA  = __expf(dtv * Ac);
            h = dA * h + dtv * uv * Bv;
            ap *= dA;
        }
        if (more) P1_STS(buf ^ 1);
        __syncthreads();
    }

    const long so = ((long)(dir * Bb + b) * NCH + chunk) * DNs + (long)(d0 + dd) * NSc + n;
    g_aprod[so] = ap;
    g_hendl[so] = h;
#undef P1_LDG
#undef P1_STS
}

__global__ void scan_p2()
{
    const int idx = blockIdx.x * 256 + threadIdx.x;
    if (idx >= 4 * DNs) return;
    const int zb = idx / DNs, dn = idx % DNs;
    const long base = (long)zb * NCH * DNs + dn;
    float hin = 0.f;
#pragma unroll
    for (int c = 0; c < NCH; c++) {
        const long o = base + (long)c * DNs;
        g_hin[o] = hin;
        hin = g_aprod[o] * hin + g_hendl[o];
    }
}

__global__ __launch_bounds__(256) void scan_p3(
    const float* __restrict__ Alog0, const float* __restrict__ D0,
    const float* __restrict__ Alog1, const float* __restrict__ D1)
{
    const int dir = blockIdx.z >> 1, b = blockIdx.z & 1;
    const int chunk = blockIdx.y;
    const int d0 = blockIdx.x * 16;
    const int tid = threadIdx.x, n = tid & 15, dd = tid >> 4;
    const float* Alog = dir ? Alog1 : Alog0;
    const float Ac = -expf(Alog[(d0 + dd) * NSc + n]);
    const float Dv = (dir ? D1 : D0)[d0 + dd];

    const long row0 = (long)b * Ls + (long)chunk * CTs;
    const float* dt_p = g_dt[dir]   + row0 * DIc + d0;
    const bf16*  uh_p = g_uhi[dir]  + row0 * DIc + d0;
    const bf16*  ul_p = g_ulo[dir]  + row0 * DIc + d0;
    const float* xd_p = g_xdbl[dir] + row0 * XDc;
    const float* z_p  = g_xz[dir]   + row0 * (2 * DIc) + DIc + d0;
    bf16* yhi_p = g_yhi[dir] + row0 * DIc + d0;
    bf16* ylo_p = g_ylo[dir] + row0 * DIc + d0;

    __shared__ float s_dt[2][TS3][16], s_u[2][TS3][16], s_B[2][TS3][16],
                     s_C[2][TS3][16], s_z[2][TS3][16], s_y[2][TS3][16];

    float r0[2], r1[2], r2[2], r3[2], r4[2];
#define P3_LDG(SEG)                                                            \
    {                                                                          \
        _Pragma("unroll")                                                      \
        for (int j = 0; j < 2; j++) {                                          \
            const int ix = tid + j * 256;                                      \
            const int t = ix >> 4, c = ix & 15;                                \
            const long tt = (long)((SEG) * TS3 + t);                           \
            r0[j] = dt_p[tt * DIc + c];                                        \
            r1[j] = __bfloat162float(uh_p[tt * DIc + c])                       \
                  + __bfloat162float(ul_p[tt * DIc + c]);                      \
            r2[j] = xd_p[tt * XDc + Rc + c];                                   \
            r3[j] = xd_p[tt * XDc + Rc + NSc + c];                             \
            r4[j] = z_p [tt * 2 * DIc + c];                                    \
        }                                                                      \
    }
#define P3_STS(BUF)                                                            \
    {                                                                          \
        _Pragma("unroll")                                                      \
        for (int j = 0; j < 2; j++) {                                          \
            const int ix = tid + j * 256;                                      \
            const int t = ix >> 4, c = ix & 15;                                \
            s_dt[BUF][t][c] = r0[j];                                           \
            s_u [BUF][t][c] = r1[j];                                           \
            s_B [BUF][t][c] = r2[j];                                           \
            s_C [BUF][t][c] = r3[j];                                           \
            s_z [BUF][t][c] = r4[j];                                           \
        }                                                                      \
    }

    P3_LDG(0); P3_STS(0); __syncthreads();

    const long so = ((long)(dir * Bb + b) * NCH + chunk) * DNs + (long)(d0 + dd) * NSc + n;
    float h = g_hin[so];

    for (int seg = 0; seg < CTs / TS3; seg++) {
        const int buf = seg & 1;
        const bool more = (seg + 1) < (CTs / TS3);
        if (more) P3_LDG(seg + 1);
#pragma unroll 8
        for (int t = 0; t < TS3; t++) {
            const float dtv = s_dt[buf][t][dd];
            const float uv  = s_u [buf][t][dd];
            const float Bv  = s_B [buf][t][n];
            const float Cv  = s_C [buf][t][n];
            const float dA  = __expf(dtv * Ac);
            h = dA * h + dtv * uv * Bv;
            float y = h * Cv;
            y += __shfl_xor_sync(0xffffffffu, y, 1);
            y += __shfl_xor_sync(0xffffffffu, y, 2);
            y += __shfl_xor_sync(0xffffffffu, y, 4);
            y += __shfl_xor_sync(0xffffffffu, y, 8);
            if (n == 0) {
                const float zv  = s_z[buf][t][dd];
                const float sig = 1.f / (1.f + __expf(-zv));
                s_y[buf][t][dd] = (y + uv * Dv) * (zv * sig);
            }
        }
        if (more) P3_STS(buf ^ 1);
        __syncthreads();
#pragma unroll
        for (int j = 0; j < 2; j++) {
            const int ix = tid + j * 256;
            const int t = ix >> 4, c = ix & 15;
            const float v = s_y[buf][t][c];
            bf16 hh, ll; split_bf16(v, hh, ll);
            const long o = (long)(seg * TS3 + t) * DIc + c;
            yhi_p[o] = hh; ylo_p[o] = ll;
        }
    }
#undef P3_LDG
#undef P3_STS
}

// ---------------- fused LayerNorm(fwd) + LayerNorm(bwd,rev) + add -> bf16 ----
__global__ void ln_combine(const float* __restrict__ g0, const float* __restrict__ b0,
                           const float* __restrict__ g1, const float* __restrict__ b1)
{
    const int row = blockIdx.x;
    const int b = row / Ls, t = row % Ls;
    const float* pf = g_do[0] + (long)row * BNc;
    const float* pb = g_do[1] + ((long)b * Ls + (Ls - 1 - t)) * BNc;
    __shared__ float2 red[128];
    const int tid = threadIdx.x;

    float vf[3], vb[3];
    float sf = 0.f, sb = 0.f;
#pragma unroll
    for (int i = 0; i < 3; i++) {
        vf[i] = pf[tid + i * 128]; sf += vf[i];
        vb[i] = pb[tid + i * 128]; sb += vb[i];
    }
    red[tid] = make_float2(sf, sb); __syncthreads();
    for (int st = 64; st > 0; st >>= 1) {
        if (tid < st) { red[tid].x += red[tid + st].x; red[tid].y += red[tid + st].y; }
        __syncthreads();
    }
    const float mf = red[0].x / (float)BNc;
    const float mb = red[0].y / (float)BNc;
    __syncthreads();

    float qf = 0.f, qb = 0.f;
#pragma unroll
    for (int i = 0; i < 3; i++) {
        float df = vf[i] - mf; qf += df * df;
        float db = vb[i] - mb; qb += db * db;
    }
    red[tid] = make_float2(qf, qb); __syncthreads();
    for (int st = 64; st > 0; st >>= 1) {
        if (tid < st) { red[tid].x += red[tid + st].x; red[tid].y += red[tid + st].y; }
        __syncthreads();
    }
    const float rf = rsqrtf(red[0].x / (float)BNc + 1e-5f);
    const float rb = rsqrtf(red[0].y / (float)BNc + 1e-5f);

#pragma unroll
    for (int i = 0; i < 3; i++) {
        const int c = tid + i * 128;
        const float v = (vf[i] - mf) * rf * g0[c] + b0[c]
                      + (vb[i] - mb) * rb * g1[c] + b1[c];
        bf16 h, l; split_bf16(v, h, l);
        g_chi[(long)row * BNc + c] = h;
        g_clo[(long)row * BNc + c] = l;
    }
}

// ------------------------------------------------------------------------------
extern "C" void kernel_launch(void* const* d_in, const int* in_sizes, int n_in,
                              void* d_out, int out_size)
{
    (void)in_sizes; (void)n_in; (void)out_size;
    const float* x      = (const float*)d_in[0];
    const float* down_W = (const float*)d_in[1];
    const float* down_b = (const float*)d_in[2];
    const float* up_W   = (const float*)d_in[3];
    const float* up_b   = (const float*)d_in[4];
    const float* F[11]; const float* Bw[11];
    for (int i = 0; i < 11; i++) { F[i] = (const float*)d_in[5 + i]; Bw[i] = (const float*)d_in[16 + i]; }

    float *p_xz, *p_xdbl, *p_do;
    cudaGetSymbolAddress((void**)&p_xz,   g_xz);
    cudaGetSymbolAddress((void**)&p_xdbl, g_xdbl);
    cudaGetSymbolAddress((void**)&p_do,   g_do);
    bf16 *xhi,*xlo,*hhi,*hlo,*uhi,*ulo,*yhi,*ylo,*chi,*clo;
    cudaGetSymbolAddress((void**)&xhi, g_xhi); cudaGetSymbolAddress((void**)&xlo, g_xlo);
    cudaGetSymbolAddress((void**)&hhi, g_hhi); cudaGetSymbolAddress((void**)&hlo, g_hlo);
    cudaGetSymbolAddress((void**)&uhi, g_uhi); cudaGetSymbolAddress((void**)&ulo, g_ulo);
    cudaGetSymbolAddress((void**)&yhi, g_yhi); cudaGetSymbolAddress((void**)&ylo, g_ylo);
    cudaGetSymbolAddress((void**)&chi, g_chi); cudaGetSymbolAddress((void**)&clo, g_clo);
    bf16 *wdhi,*wdlo,*wihi,*wilo,*wxhi,*wxlo,*wohi,*wolo,*wuhi,*wulo;
    cudaGetSymbolAddress((void**)&wdhi, g_wdhi); cudaGetSymbolAddress((void**)&wdlo, g_wdlo);
    cudaGetSymbolAddress((void**)&wihi, g_wihi); cudaGetSymbolAddress((void**)&wilo, g_wilo);
    cudaGetSymbolAddress((void**)&wxhi, g_wxhi); cudaGetSymbolAddress((void**)&wxlo, g_wxlo);
    cudaGetSymbolAddress((void**)&wohi, g_wohi); cudaGetSymbolAddress((void**)&wolo, g_wolo);
    cudaGetSymbolAddress((void**)&wuhi, g_wuhi); cudaGetSymbolAddress((void**)&wulo, g_wulo);

    cudaFuncSetAttribute(tc_gemm, cudaFuncAttributeMaxDynamicSharedMemorySize, GEMM_SMEM);

    // 1) input split
    split_pass<<<(BLr*DIc + 255)/256, 256>>>(x, xhi, xlo, (long)BLr*DIc);

    // 2) ALL weight splits in one launch
    SplitJobs J;
    J.src[0] = down_W; J.hi[0] = wdhi;             J.lo[0] = wdlo;             J.K[0] = DIc; J.N[0] = BNc;
    J.src[1] = F[0];   J.hi[1] = wihi;             J.lo[1] = wilo;             J.K[1] = BNc; J.N[1] = 2*DIc;
    J.src[2] = Bw[0];  J.hi[2] = wihi + 2*DIc*BNc; J.lo[2] = wilo + 2*DIc*BNc; J.K[2] = BNc; J.N[2] = 2*DIc;
    J.src[3] = F[3];   J.hi[3] = wxhi;             J.lo[3] = wxlo;             J.K[3] = DIc; J.N[3] = XDc;
    J.src[4] = Bw[3];  J.hi[4] = wxhi + XDc*DIc;   J.lo[4] = wxlo + XDc*DIc;   J.K[4] = DIc; J.N[4] = XDc;
    J.src[5] = F[8];   J.hi[5] = wohi;             J.lo[5] = wolo;             J.K[5] = DIc; J.N[5] = BNc;
    J.src[6] = Bw[8];  J.hi[6] = wohi + BNc*DIc;   J.lo[6] = wolo + BNc*DIc;   J.K[6] = DIc; J.N[6] = BNc;
    J.src[7] = up_W;   J.hi[7] = wuhi;             J.lo[7] = wulo;             J.K[7] = BNc; J.N[7] = DIc;
    wsplit_all<<<dim3((2*DIc*BNc + 255)/256, 8), 256>>>(J);

    // 3) down GEMM: h = x @ down_W + down_b -> bf16 hi/lo (8192x384, K=768)
    tc_gemm<<<dim3(3, 64, 1), 256, GEMM_SMEM>>>(xhi, xlo, 0, wdhi, wdlo, wdhi, wdlo,
                                                down_b, nullptr, hhi, hlo, 0,
                                                BNc, DIc, 0);

    // 4) in GEMM: xz[dir] = h(rev dir1) @ in_W[dir] -> f32 (8192x1536, K=384)
    tc_gemm<<<dim3(12, 64, 2), 256, GEMM_SMEM>>>(hhi, hlo, 0,
                                                 wihi, wilo, wihi + 2*DIc*BNc, wilo + 2*DIc*BNc,
                                                 nullptr, p_xz, nullptr, nullptr, (long)BLr*2*DIc,
                                                 2*DIc, BNc, 1);

    // 5) u = silu(conv(xs)) -> bf16 hi/lo
    conv_silu<<<dim3((BLr * DIc + 255) / 256, 2), 256>>>(F[1], F[2], Bw[1], Bw[2]);

    // 6) x_dbl = u @ xproj_W -> f32 (8192x56, K=768)
    tc_gemm<<<dim3(1, 64, 2), 256, GEMM_SMEM>>>(uhi, ulo, (long)BLr*DIc,
                                                wxhi, wxlo, wxhi + XDc*DIc, wxlo + XDc*DIc,
                                                nullptr, p_xdbl, nullptr, nullptr, (long)BLr*XDc,
                                                XDc, DIc, 0);

    // 7) dt
    dt_kernel<<<dim3(BLr / 16, 2), 256>>>(F[4], F[5], Bw[4], Bw[5]);

    // 8-10) chunked scan
    scan_p1<<<dim3(DIc / 16, NCH, 4), 256>>>(F[6], Bw[6]);
    scan_p2<<<(4 * DNs + 255) / 256, 256>>>();
    scan_p3<<<dim3(DIc / 16, NCH, 4), 256>>>(F[6], F[7], Bw[6], Bw[7]);

    // 11) out[dir] = y @ out_W -> f32 (8192x384, K=768)
    tc_gemm<<<dim3(3, 64, 2), 256, GEMM_SMEM>>>(yhi, ylo, (long)BLr*DIc,
                                                wohi, wolo, wohi + BNc*DIc, wolo + BNc*DIc,
                                                nullptr, p_do, nullptr, nullptr, (long)BLr*BNc,
                                                BNc, DIc, 0);

    // 12) fused ln + combine -> bf16 hi/lo
    ln_combine<<<BLr, 128>>>(F[9], F[10], Bw[9], Bw[10]);

    // 13) out = comb @ up_W + up_b -> f32 (8192x768, K=384)
    tc_gemm<<<dim3(6, 64, 1), 256, GEMM_SMEM>>>(chi, clo, 0, wuhi, wulo, wuhi, wulo,
                                                up_b, (float*)d_out, nullptr, nullptr, 0,
                                                DIc, BNc, 0);
}

// round 16
// speedup vs baseline: 1.0317x; 1.0317x over previous
#include <cuda_runtime.h>
#include <cuda_bf16.h>
#include <math.h>
#include <stdint.h>

#define Bb   2
#define Ls   4096
#define BLr  (Bb*Ls)          // 8192 rows
#define BNc  384
#define DIc  768
#define NSc  16
#define DCc  4
#define Rc   24
#define XDc  (Rc + 2*NSc)     // 56

#define NCH  16
#define CTs  (Ls/NCH)         // 256
#define TS1  64
#define TS3  32
#define DNs  (DIc*NSc)        // 12288

typedef __nv_bfloat16 bf16;

// ---------------- scratch (static device arrays; no allocation) -------------
__device__ float g_xz  [2][BLr*2*DIc];
__device__ float g_xdbl[2][BLr*XDc];
__device__ float g_dt  [2][BLr*DIc];
__device__ float g_do  [2][BLr*BNc];
__device__ float g_aprod[4*NCH*DNs];
__device__ float g_hendl[4*NCH*DNs];
__device__ float g_hin  [4*NCH*DNs];

// bf16 hi/lo activation operands
__device__ bf16 g_xhi[BLr*DIc],  g_xlo[BLr*DIc];
__device__ bf16 g_hhi[BLr*BNc],  g_hlo[BLr*BNc];
__device__ bf16 g_uhi[2][BLr*DIc], g_ulo[2][BLr*DIc];
__device__ bf16 g_yhi[2][BLr*DIc], g_ylo[2][BLr*DIc];
__device__ bf16 g_chi[BLr*BNc],  g_clo[BLr*BNc];

// transposed bf16 hi/lo weights [N,K]
__device__ bf16 g_wdhi[BNc*DIc],      g_wdlo[BNc*DIc];
__device__ bf16 g_wihi[2][2*DIc*BNc], g_wilo[2][2*DIc*BNc];
__device__ bf16 g_wxhi[2][XDc*DIc],   g_wxlo[2][XDc*DIc];
__device__ bf16 g_wohi[2][BNc*DIc],   g_wolo[2][BNc*DIc];
__device__ bf16 g_wuhi[DIc*BNc],      g_wulo[DIc*BNc];

// ---------------- helpers ------------------------------------------------------
__device__ __forceinline__ void split_bf16(float x, bf16& h, bf16& l){
    h = __float2bfloat16_rn(x);
    l = __float2bfloat16_rn(x - __bfloat162float(h));
}
__device__ __forceinline__ void mma16n8k16(float* d, const uint32_t* a, const uint32_t* b){
    asm volatile(
        "mma.sync.aligned.m16n8k16.row.col.f32.bf16.bf16.f32 "
        "{%0,%1,%2,%3}, {%4,%5,%6,%7}, {%8,%9}, {%0,%1,%2,%3};"
        : "+f"(d[0]), "+f"(d[1]), "+f"(d[2]), "+f"(d[3])
        : "r"(a[0]), "r"(a[1]), "r"(a[2]), "r"(a[3]), "r"(b[0]), "r"(b[1]));
}
__device__ __forceinline__ void ldsm4(uint32_t* r, uint32_t addr){
    asm volatile("ldmatrix.sync.aligned.m8n8.x4.shared.b16 {%0,%1,%2,%3}, [%4];"
        : "=r"(r[0]), "=r"(r[1]), "=r"(r[2]), "=r"(r[3]) : "r"(addr));
}
__device__ __forceinline__ void cp16(uint32_t dst, const void* src, int sz){
    asm volatile("cp.async.cg.shared.global [%0], [%1], 16, %2;\n"
                 :: "r"(dst), "l"(src), "r"(sz) : "memory");
}
#define CP_COMMIT() asm volatile("cp.async.commit_group;\n" ::: "memory")
#define CP_WAIT(n)  asm volatile("cp.async.wait_group %0;\n" :: "n"(n) : "memory")

// ---------------- bf16 GEMM, 128x128 tile, KT=64, 3-stage cp.async + LDSM ----
// Row = 36 u32 (144B): 64 bf16 ks (128B data) + 16B pad -> ldmatrix conflict-free.
// Stage layout (u32): A hi [0,PART_U), A lo [PART_U,2P), B hi [2P,3P), B lo [3P,4P).
#define ROW_U   36
#define PART_U  (128*ROW_U)        // 4608
#define STAGE_U (4*PART_U)         // 18432
#define GEMM_SMEM (3*STAGE_U*4)    // 221184 bytes

__global__ __launch_bounds__(256, 1) void tc_gemm(
    const bf16* __restrict__ Ahi, const bf16* __restrict__ Alo, long sA,
    const bf16* __restrict__ Whi0, const bf16* __restrict__ Wlo0,
    const bf16* __restrict__ Whi1, const bf16* __restrict__ Wlo1,
    const float* __restrict__ bias,
    float* __restrict__ Cf, bf16* __restrict__ Chi, bf16* __restrict__ Clo, long sC,
    int N, int K, int revz)
{
    extern __shared__ uint32_t sm[];
    const uint32_t smb = (uint32_t)__cvta_generic_to_shared(sm);

    const int z = blockIdx.z;
    const bf16* __restrict__ Whi = z ? Whi1 : Whi0;
    const bf16* __restrict__ Wlo = z ? Wlo1 : Wlo0;
    Ahi += (long)z * sA;  Alo += (long)z * sA;
    if (Cf)  Cf  += (long)z * sC;
    if (Chi) { Chi += (long)z * sC; Clo += (long)z * sC; }

    const int tid  = threadIdx.x;
    const int lane = tid & 31;
    const int wid  = tid >> 5;
    const int warpM = wid & 3;
    const int warpN = wid >> 2;
    const int gid = lane >> 2;
    const int tig = lane & 3;

    const int crow = blockIdx.y * 128;
    const int ccol = blockIdx.x * 128;

    // ldmatrix per-thread base byte offsets (within a stage)
    const uint32_t aOff = (uint32_t)((warpM * 32 + (lane & 15)) * 144 + (lane >> 4) * 16);
    const uint32_t bOff = (uint32_t)((warpN * 64 + (lane & 7) + ((lane >> 4) << 3)) * 144
                                     + ((lane >> 3) & 1) * 16);

    // cp.async: 16 chunks of 16B per thread per stage.
    const int segA = tid & 7;
    const long dAlo = Alo - Ahi;
    const long dWlo = Wlo - Whi;
    const bf16* aP[4]; const bf16* bP[4];
    uint32_t dAb[4], dBb[4]; int szB[4];
#pragma unroll
    for (int j = 0; j < 4; j++) {
        const int row = (tid >> 3) + 32 * j;
        int gRow = crow + row;
        if (revz && z == 1) {
            int bb = gRow / Ls, t = gRow - bb * Ls;
            gRow = bb * Ls + (Ls - 1 - t);
        }
        aP[j] = Ahi + (long)gRow * K + segA * 8;
        dAb[j] = smb + (uint32_t)(row * ROW_U + segA * 4) * 4u;
        const int ng = ccol + row;
        bP[j] = Whi + (long)ng * K + segA * 8;
        szB[j] = (ng < N) ? 16 : 0;
        dBb[j] = smb + (uint32_t)(2 * PART_U + row * ROW_U + segA * 4) * 4u;   // B hi @ 2*PART_U
    }

#define ISSUE(KT, S)                                                           \
    {                                                                          \
        const uint32_t so = (uint32_t)(S) * STAGE_U * 4u;                      \
        const int ko = (KT) * 64;                                              \
        _Pragma("unroll")                                                      \
        for (int j = 0; j < 4; j++) {                                          \
            cp16(dAb[j] + so,               aP[j] + ko,        16);            \
            cp16(dAb[j] + so + PART_U * 4u, aP[j] + dAlo + ko, 16);            \
            cp16(dBb[j] + so,               bP[j] + ko,        szB[j]);        \
            cp16(dBb[j] + so + PART_U * 4u, bP[j] + dWlo + ko, szB[j]);        \
        }                                                                      \
        CP_COMMIT();                                                           \
    }

    float acc[2][8][4];
#pragma unroll
    for (int m = 0; m < 2; m++)
#pragma unroll
        for (int n = 0; n < 8; n++)
#pragma unroll
            for (int q = 0; q < 4; q++) acc[m][n][q] = 0.f;

    const int nkt = K >> 6;    // KT=64

    ISSUE(0, 0);
    if (nkt > 1) ISSUE(1, 1);

    int s = 0;
    for (int kt = 0; kt < nkt; kt++) {
        if (kt + 1 < nkt) { CP_WAIT(1); }
        else              { CP_WAIT(0); }
        __syncthreads();

        const uint32_t stg = smb + (uint32_t)s * STAGE_U * 4u;
        const uint32_t aHi = stg + aOff;
        const uint32_t aLo = aHi + PART_U * 4u;
        const uint32_t bHi = stg + 2u * PART_U * 4u + bOff;    // B hi @ 2*PART_U u32
        const uint32_t bLo = bHi + PART_U * 4u;

#pragma unroll
        for (int ks = 0; ks < 4; ks++) {
            const uint32_t ko = (uint32_t)ks * 32u;
            uint32_t ah[2][4], al[2][4];
            uint32_t bh[4][4], bl[4][4];
#pragma unroll
            for (int m = 0; m < 2; m++) {
                ldsm4(ah[m], aHi + m * 2304u + ko);
                ldsm4(al[m], aLo + m * 2304u + ko);
            }
#pragma unroll
            for (int g2 = 0; g2 < 4; g2++) {
                ldsm4(bh[g2], bHi + g2 * 2304u + ko);
                ldsm4(bl[g2], bLo + g2 * 2304u + ko);
            }
#pragma unroll
            for (int g2 = 0; g2 < 4; g2++)
#pragma unroll
                for (int sub = 0; sub < 2; sub++)
#pragma unroll
                    for (int m = 0; m < 2; m++)
                        mma16n8k16(acc[m][g2*2+sub], ah[m], &bh[g2][sub*2]);
#pragma unroll
            for (int g2 = 0; g2 < 4; g2++)
#pragma unroll
                for (int sub = 0; sub < 2; sub++)
#pragma unroll
                    for (int m = 0; m < 2; m++)
                        mma16n8k16(acc[m][g2*2+sub], ah[m], &bl[g2][sub*2]);
#pragma unroll
            for (int g2 = 0; g2 < 4; g2++)
#pragma unroll
                for (int sub = 0; sub < 2; sub++)
#pragma unroll
                    for (int m = 0; m < 2; m++)
                        mma16n8k16(acc[m][g2*2+sub], al[m], &bh[g2][sub*2]);
        }

        if (kt + 2 < nkt) {
            const int s2 = (s + 2 >= 3) ? s - 1 : s + 2;
            ISSUE(kt + 2, s2);
        }
        s = (s + 1 == 3) ? 0 : s + 1;
    }

    // epilogue
#pragma unroll
    for (int m = 0; m < 2; m++) {
        const int r0 = crow + warpM * 32 + m * 16 + gid;
#pragma unroll
        for (int n = 0; n < 8; n++) {
            const int c = ccol + warpN * 64 + n * 8 + tig * 2;
            if (c < N) {
                float2 v0 = make_float2(acc[m][n][0], acc[m][n][1]);
                float2 v1 = make_float2(acc[m][n][2], acc[m][n][3]);
                if (bias) {
                    const float b0 = bias[c], b1 = bias[c + 1];
                    v0.x += b0; v0.y += b1; v1.x += b0; v1.y += b1;
                }
                if (Cf) {
                    *(float2*)&Cf[(long)r0 * N + c]       = v0;
                    *(float2*)&Cf[(long)(r0 + 8) * N + c] = v1;
                } else {
                    bf16 h0,l0,h1,l1;
                    split_bf16(v0.x, h0, l0); split_bf16(v0.y, h1, l1);
                    *(__nv_bfloat162*)&Chi[(long)r0 * N + c] = __nv_bfloat162(h0, h1);
                    *(__nv_bfloat162*)&Clo[(long)r0 * N + c] = __nv_bfloat162(l0, l1);
                    split_bf16(v1.x, h0, l0); split_bf16(v1.y, h1, l1);
                    *(__nv_bfloat162*)&Chi[(long)(r0 + 8) * N + c] = __nv_bfloat162(h0, h1);
                    *(__nv_bfloat162*)&Clo[(long)(r0 + 8) * N + c] = __nv_bfloat162(l0, l1);
                }
            }
        }
    }
#undef ISSUE
}

// ---------------- pre-split passes -------------------------------------------
__global__ void split_pass(const float* __restrict__ src, bf16* __restrict__ hi,
                           bf16* __restrict__ lo, long n)
{
    long i = (long)blockIdx.x * blockDim.x + threadIdx.x;
    if (i >= n) return;
    bf16 h, l; split_bf16(src[i], h, l);
    hi[i] = h; lo[i] = l;
}

struct SplitJobs {
    const float* src[8];
    bf16* hi[8];
    bf16* lo[8];
    int K[8];
    int N[8];
};
__global__ void wsplit_all(SplitJobs J)
{
    const int j = blockIdx.y;
    const int K = J.K[j], N = J.N[j];
    long i = (long)blockIdx.x * blockDim.x + threadIdx.x;
    if (i >= (long)N * K) return;
    int n = (int)(i / K), k = (int)(i % K);
    bf16 h, l; split_bf16(J.src[j][(long)k * N + n], h, l);
    J.hi[j][i] = h; J.lo[j][i] = l;
}

// ---------------- causal depthwise conv (DC=4) + SiLU -> bf16 hi/lo ----------
__global__ void conv_silu(const float* __restrict__ cw0, const float* __restrict__ cb0,
                          const float* __restrict__ cw1, const float* __restrict__ cb1)
{
    const int dir = blockIdx.y;
    long idx = (long)blockIdx.x * blockDim.x + threadIdx.x;
    if (idx >= (long)BLr * DIc) return;
    const int d = (int)(idx % DIc);
    const long row = idx / DIc;
    const int t = (int)(row % Ls);
    const float* cw = dir ? cw1 : cw0;
    const float* cb = dir ? cb1 : cb0;
    const float* xs = g_xz[dir];

    float s = cb[d];
#pragma unroll
    for (int k = 0; k < DCc; k++) {
        int tt = t - (DCc - 1) + k;
        if (tt >= 0) s += xs[(row - t + tt) * (2 * DIc) + d] * cw[d * DCc + k];
    }
    float sig = 1.f / (1.f + __expf(-s));
    float v = s * sig;
    bf16 h, l; split_bf16(v, h, l);
    g_uhi[dir][idx] = h; g_ulo[dir][idx] = l;
}

// ---------------- dt = softplus(dt_raw @ dt_W + dt_b) ------------------------
__global__ __launch_bounds__(256) void dt_kernel(
    const float* __restrict__ W0, const float* __restrict__ b0,
    const float* __restrict__ W1, const float* __restrict__ b1)
{
    const int dir = blockIdx.y;
    const int row0 = blockIdx.x * 16;
    const int tid = threadIdx.x;
    __shared__ float xd[16][Rc];
    for (int i = tid; i < 16 * Rc; i += 256) {
        int r = i / Rc, c = i - r * Rc;
        xd[r][c] = g_xdbl[dir][(long)(row0 + r) * XDc + c];
    }
    __syncthreads();
    const float* W  = dir ? W1 : W0;
    const float* bb = dir ? b1 : b0;
    for (int d = tid; d < DIc; d += 256) {
        float w[Rc];
#pragma unroll
        for (int r = 0; r < Rc; r++) w[r] = W[r * DIc + d];
        const float bias = bb[d];
#pragma unroll 4
        for (int rr = 0; rr < 16; rr++) {
            float s = bias;
#pragma unroll
            for (int r = 0; r < Rc; r++) s += xd[rr][r] * w[r];
            float sp = fmaxf(s, 0.f) + log1pf(__expf(-fabsf(s)));
            g_dt[dir][(long)(row0 + rr) * DIc + d] = sp;
        }
    }
}

// ---------------- chunked selective scan --------------------------------------
__global__ __launch_bounds__(256) void scan_p1(
    const float* __restrict__ Alog0, const float* __restrict__ Alog1)
{
    const int dir = blockIdx.z >> 1, b = blockIdx.z & 1;
    const int chunk = blockIdx.y;
    const int d0 = blockIdx.x * 16;
    const int tid = threadIdx.x, n = tid & 15, dd = tid >> 4;
    const float* Alog = dir ? Alog1 : Alog0;
    const float Ac = -expf(Alog[(d0 + dd) * NSc + n]);

    const long row0 = (long)b * Ls + (long)chunk * CTs;
    const float* dt_p = g_dt[dir]   + row0 * DIc + d0;
    const bf16*  uh_p = g_uhi[dir]  + row0 * DIc + d0;
    const bf16*  ul_p = g_ulo[dir]  + row0 * DIc + d0;
    const float* xd_p = g_xdbl[dir] + row0 * XDc;

    __shared__ float s_dt[2][TS1][16], s_u[2][TS1][16], s_B[2][TS1][16];

    float r0[4], r1[4], r2[4];
#define P1_LDG(SEG)                                                            \
    {                                                                          \
        _Pragma("unroll")                                                      \
        for (int j = 0; j < 4; j++) {                                          \
            const int ix = tid + j * 256;                                      \
            const int t = ix >> 4, c = ix & 15;                                \
            const long tt = (long)((SEG) * TS1 + t);                           \
            r0[j] = dt_p[tt * DIc + c];                                        \
            r1[j] = __bfloat162float(uh_p[tt * DIc + c])                       \
                  + __bfloat162float(ul_p[tt * DIc + c]);                      \
            r2[j] = xd_p[tt * XDc + Rc + c];                                   \
        }                                                                      \
    }
#define P1_STS(BUF)                                                            \
    {                                                                          \
        _Pragma("unroll")                                                      \
        for (int j = 0; j < 4; j++) {                                          \
            const int ix = tid + j * 256;                                      \
            const int t = ix >> 4, c = ix & 15;                                \
            s_dt[BUF][t][c] = r0[j];                                           \
            s_u [BUF][t][c] = r1[j];                                           \
            s_B [BUF][t][c] = r2[j];                                           \
        }                                                                      \
    }

    P1_LDG(0); P1_STS(0); __syncthreads();

    float h = 0.f, ap = 1.f;
    for (int seg = 0; seg < CTs / TS1; seg++) {
        const int buf = seg & 1;
        const bool more = (seg + 1) < (CTs / TS1);
        if (more) P1_LDG(seg + 1);
#pragma unroll 8
        for (int t = 0; t < TS1; t++) {
            const float dtv = s_dt[buf][t][dd];
            const float uv  = s_u [buf][t][dd];
            const float Bv  = s_B [buf][t][n];
            const float dA  = __expf(dtv * Ac);
            h = dA * h + dtv * uv * Bv;
            ap *= dA;
        }
        if (more) P1_STS(buf ^ 1);
        __syncthreads();
    }

    const long so = ((long)(dir * Bb + b) * NCH + chunk) * DNs + (long)(d0 + dd) * NSc + n;
    g_aprod[so] = ap;
    g_hendl[so] = h;
#undef P1_LDG
#undef P1_STS
}

__global__ void scan_p2()
{
    const int idx = blockIdx.x * 256 + threadIdx.x;
    if (idx >= 4 * DNs) return;
    const int zb = idx / DNs, dn = idx % DNs;
    const long base = (long)zb * NCH * DNs + dn;
    float hin = 0.f;
#pragma unroll
    for (int c = 0; c < NCH; c++) {
        const long o = base + (long)c * DNs;
        g_hin[o] = hin;
        hin = g_aprod[o] * hin + g_hendl[o];
    }
}

__global__ __launch_bounds__(256) void scan_p3(
    const float* __restrict__ Alog0, const float* __restrict__ D0,
    const float* __restrict__ Alog1, const float* __restrict__ D1)
{
    const int dir = blockIdx.z >> 1, b = blockIdx.z & 1;
    const int chunk = blockIdx.y;
    const int d0 = blockIdx.x * 16;
    const int tid = threadIdx.x, n = tid & 15, dd = tid >> 4;
    const float* Alog = dir ? Alog1 : Alog0;
    const float Ac = -expf(Alog[(d0 + dd) * NSc + n]);
    const float Dv = (dir ? D1 : D0)[d0 + dd];

    const long row0 = (long)b * Ls + (long)chunk * CTs;
    const float* dt_p = g_dt[dir]   + row0 * DIc + d0;
    const bf16*  uh_p = g_uhi[dir]  + row0 * DIc + d0;
    const bf16*  ul_p = g_ulo[dir]  + row0 * DIc + d0;
    const float* xd_p = g_xdbl[dir] + row0 * XDc;
    const float* z_p  = g_xz[dir]   + row0 * (2 * DIc) + DIc + d0;
    bf16* yhi_p = g_yhi[dir] + row0 * DIc + d0;
    bf16* ylo_p = g_ylo[dir] + row0 * DIc + d0;

    __shared__ float s_dt[2][TS3][16], s_u[2][TS3][16], s_B[2][TS3][16],
                     s_C[2][TS3][16], s_z[2][TS3][16], s_y[2][TS3][16];

    float r0[2], r1[2], r2[2], r3[2], r4[2];
#define P3_LDG(SEG)                                                            \
    {                                                                          \
        _Pragma("unroll")                                                      \
        for (int j = 0; j < 2; j++) {                                          \
            const int ix = tid + j * 256;                                      \
            const int t = ix >> 4, c = ix & 15;                                \
            const long tt = (long)((SEG) * TS3 + t);                           \
            r0[j] = dt_p[tt * DIc + c];                                        \
            r1[j] = __bfloat162float(uh_p[tt * DIc + c])                       \
                  + __bfloat162float(ul_p[tt * DIc + c]);                      \
            r2[j] = xd_p[tt * XDc + Rc + c];                                   \
            r3[j] = xd_p[tt * XDc + Rc + NSc + c];                             \
            r4[j] = z_p [tt * 2 * DIc + c];                                    \
        }                                                                      \
    }
#define P3_STS(BUF)                                                            \
    {                                                                          \
        _Pragma("unroll")                                                      \
        for (int j = 0; j < 2; j++) {                                          \
            const int ix = tid + j * 256;                                      \
            const int t = ix >> 4, c = ix & 15;                                \
            s_dt[BUF][t][c] = r0[j];                                           \
            s_u [BUF][t][c] = r1[j];                                           \
            s_B [BUF][t][c] = r2[j];                                           \
            s_C [BUF][t][c] = r3[j];                                           \
            s_z [BUF][t][c] = r4[j];                                           \
        }                                                                      \
    }

    P3_LDG(0); P3_STS(0); __syncthreads();

    const long so = ((long)(dir * Bb + b) * NCH + chunk) * DNs + (long)(d0 + dd) * NSc + n;
    float h = g_hin[so];

    for (int seg = 0; seg < CTs / TS3; seg++) {
        const int buf = seg & 1;
        const bool more = (seg + 1) < (CTs / TS3);
        if (more) P3_LDG(seg + 1);
#pragma unroll 8
        for (int t = 0; t < TS3; t++) {
            const float dtv = s_dt[buf][t][dd];
            const float uv  = s_u [buf][t][dd];
            const float Bv  = s_B [buf][t][n];
            const float Cv  = s_C [buf][t][n];
            const float dA  = __expf(dtv * Ac);
            h = dA * h + dtv * uv * Bv;
            float y = h * Cv;
            y += __shfl_xor_sync(0xffffffffu, y, 1);
            y += __shfl_xor_sync(0xffffffffu, y, 2);
            y += __shfl_xor_sync(0xffffffffu, y, 4);
            y += __shfl_xor_sync(0xffffffffu, y, 8);
            if (n == 0) {
                const float zv  = s_z[buf][t][dd];
                const float sig = 1.f / (1.f + __expf(-zv));
                s_y[buf][t][dd] = (y + uv * Dv) * (zv * sig);
            }
        }
        if (more) P3_STS(buf ^ 1);
        __syncthreads();
#pragma unroll
        for (int j = 0; j < 2; j++) {
            const int ix = tid + j * 256;
            const int t = ix >> 4, c = ix & 15;
            const float v = s_y[buf][t][c];
            bf16 hh, ll; split_bf16(v, hh, ll);
            const long o = (long)(seg * TS3 + t) * DIc + c;
            yhi_p[o] = hh; ylo_p[o] = ll;
        }
    }
#undef P3_LDG
#undef P3_STS
}

// ---------------- fused LayerNorm(fwd) + LayerNorm(bwd,rev) + add -> bf16 ----
__global__ void ln_combine(const float* __restrict__ g0, const float* __restrict__ b0,
                           const float* __restrict__ g1, const float* __restrict__ b1)
{
    const int row = blockIdx.x;
    const int b = row / Ls, t = row % Ls;
    const float* pf = g_do[0] + (long)row * BNc;
    const float* pb = g_do[1] + ((long)b * Ls + (Ls - 1 - t)) * BNc;
    __shared__ float2 red[128];
    const int tid = threadIdx.x;

    float vf[3], vb[3];
    float sf = 0.f, sb = 0.f;
#pragma unroll
    for (int i = 0; i < 3; i++) {
        vf[i] = pf[tid + i * 128]; sf += vf[i];
        vb[i] = pb[tid + i * 128]; sb += vb[i];
    }
    red[tid] = make_float2(sf, sb); __syncthreads();
    for (int st = 64; st > 0; st >>= 1) {
        if (tid < st) { red[tid].x += red[tid + st].x; red[tid].y += red[tid + st].y; }
        __syncthreads();
    }
    const float mf = red[0].x / (float)BNc;
    const float mb = red[0].y / (float)BNc;
    __syncthreads();

    float qf = 0.f, qb = 0.f;
#pragma unroll
    for (int i = 0; i < 3; i++) {
        float df = vf[i] - mf; qf += df * df;
        float db = vb[i] - mb; qb += db * db;
    }
    red[tid] = make_float2(qf, qb); __syncthreads();
    for (int st = 64; st > 0; st >>= 1) {
        if (tid < st) { red[tid].x += red[tid + st].x; red[tid].y += red[tid + st].y; }
        __syncthreads();
    }
    const float rf = rsqrtf(red[0].x / (float)BNc + 1e-5f);
    const float rb = rsqrtf(red[0].y / (float)BNc + 1e-5f);

#pragma unroll
    for (int i = 0; i < 3; i++) {
        const int c = tid + i * 128;
        const float v = (vf[i] - mf) * rf * g0[c] + b0[c]
                      + (vb[i] - mb) * rb * g1[c] + b1[c];
        bf16 h, l; split_bf16(v, h, l);
        g_chi[(long)row * BNc + c] = h;
        g_clo[(long)row * BNc + c] = l;
    }
}

// ------------------------------------------------------------------------------
extern "C" void kernel_launch(void* const* d_in, const int* in_sizes, int n_in,
                              void* d_out, int out_size)
{
    (void)in_sizes; (void)n_in; (void)out_size;
    const float* x      = (const float*)d_in[0];
    const float* down_W = (const float*)d_in[1];
    const float* down_b = (const float*)d_in[2];
    const float* up_W   = (const float*)d_in[3];
    const float* up_b   = (const float*)d_in[4];
    const float* F[11]; const float* Bw[11];
    for (int i = 0; i < 11; i++) { F[i] = (const float*)d_in[5 + i]; Bw[i] = (const float*)d_in[16 + i]; }

    float *p_xz, *p_xdbl, *p_do;
    cudaGetSymbolAddress((void**)&p_xz,   g_xz);
    cudaGetSymbolAddress((void**)&p_xdbl, g_xdbl);
    cudaGetSymbolAddress((void**)&p_do,   g_do);
    bf16 *xhi,*xlo,*hhi,*hlo,*uhi,*ulo,*yhi,*ylo,*chi,*clo;
    cudaGetSymbolAddress((void**)&xhi, g_xhi); cudaGetSymbolAddress((void**)&xlo, g_xlo);
    cudaGetSymbolAddress((void**)&hhi, g_hhi); cudaGetSymbolAddress((void**)&hlo, g_hlo);
    cudaGetSymbolAddress((void**)&uhi, g_uhi); cudaGetSymbolAddress((void**)&ulo, g_ulo);
    cudaGetSymbolAddress((void**)&yhi, g_yhi); cudaGetSymbolAddress((void**)&ylo, g_ylo);
    cudaGetSymbolAddress((void**)&chi, g_chi); cudaGetSymbolAddress((void**)&clo, g_clo);
    bf16 *wdhi,*wdlo,*wihi,*wilo,*wxhi,*wxlo,*wohi,*wolo,*wuhi,*wulo;
    cudaGetSymbolAddress((void**)&wdhi, g_wdhi); cudaGetSymbolAddress((void**)&wdlo, g_wdlo);
    cudaGetSymbolAddress((void**)&wihi, g_wihi); cudaGetSymbolAddress((void**)&wilo, g_wilo);
    cudaGetSymbolAddress((void**)&wxhi, g_wxhi); cudaGetSymbolAddress((void**)&wxlo, g_wxlo);
    cudaGetSymbolAddress((void**)&wohi, g_wohi); cudaGetSymbolAddress((void**)&wolo, g_wolo);
    cudaGetSymbolAddress((void**)&wuhi, g_wuhi); cudaGetSymbolAddress((void**)&wulo, g_wulo);

    cudaFuncSetAttribute(tc_gemm, cudaFuncAttributeMaxDynamicSharedMemorySize, GEMM_SMEM);

    // 1) input split
    split_pass<<<(BLr*DIc + 255)/256, 256>>>(x, xhi, xlo, (long)BLr*DIc);

    // 2) ALL weight splits in one launch
    SplitJobs J;
    J.src[0] = down_W; J.hi[0] = wdhi;             J.lo[0] = wdlo;             J.K[0] = DIc; J.N[0] = BNc;
    J.src[1] = F[0];   J.hi[1] = wihi;             J.lo[1] = wilo;             J.K[1] = BNc; J.N[1] = 2*DIc;
    J.src[2] = Bw[0];  J.hi[2] = wihi + 2*DIc*BNc; J.lo[2] = wilo + 2*DIc*BNc; J.K[2] = BNc; J.N[2] = 2*DIc;
    J.src[3] = F[3];   J.hi[3] = wxhi;             J.lo[3] = wxlo;             J.K[3] = DIc; J.N[3] = XDc;
    J.src[4] = Bw[3];  J.hi[4] = wxhi + XDc*DIc;   J.lo[4] = wxlo + XDc*DIc;   J.K[4] = DIc; J.N[4] = XDc;
    J.src[5] = F[8];   J.hi[5] = wohi;             J.lo[5] = wolo;             J.K[5] = DIc; J.N[5] = BNc;
    J.src[6] = Bw[8];  J.hi[6] = wohi + BNc*DIc;   J.lo[6] = wolo + BNc*DIc;   J.K[6] = DIc; J.N[6] = BNc;
    J.src[7] = up_W;   J.hi[7] = wuhi;             J.lo[7] = wulo;             J.K[7] = BNc; J.N[7] = DIc;
    wsplit_all<<<dim3((2*DIc*BNc + 255)/256, 8), 256>>>(J);

    // 3) down GEMM: h = x @ down_W + down_b -> bf16 hi/lo (8192x384, K=768)
    tc_gemm<<<dim3(3, 64, 1), 256, GEMM_SMEM>>>(xhi, xlo, 0, wdhi, wdlo, wdhi, wdlo,
                                                down_b, nullptr, hhi, hlo, 0,
                                                BNc, DIc, 0);

    // 4) in GEMM: xz[dir] = h(rev dir1) @ in_W[dir] -> f32 (8192x1536, K=384)
    tc_gemm<<<dim3(12, 64, 2), 256, GEMM_SMEM>>>(hhi, hlo, 0,
                                                 wihi, wilo, wihi + 2*DIc*BNc, wilo + 2*DIc*BNc,
                                                 nullptr, p_xz, nullptr, nullptr, (long)BLr*2*DIc,
                                                 2*DIc, BNc, 1);

    // 5) u = silu(conv(xs)) -> bf16 hi/lo
    conv_silu<<<dim3((BLr * DIc + 255) / 256, 2), 256>>>(F[1], F[2], Bw[1], Bw[2]);

    // 6) x_dbl = u @ xproj_W -> f32 (8192x56, K=768)
    tc_gemm<<<dim3(1, 64, 2), 256, GEMM_SMEM>>>(uhi, ulo, (long)BLr*DIc,
                                                wxhi, wxlo, wxhi + XDc*DIc, wxlo + XDc*DIc,
                                                nullptr, p_xdbl, nullptr, nullptr, (long)BLr*XDc,
                                                XDc, DIc, 0);

    // 7) dt
    dt_kernel<<<dim3(BLr / 16, 2), 256>>>(F[4], F[5], Bw[4], Bw[5]);

    // 8-10) chunked scan
    scan_p1<<<dim3(DIc / 16, NCH, 4), 256>>>(F[6], Bw[6]);
    scan_p2<<<(4 * DNs + 255) / 256, 256>>>();
    scan_p3<<<dim3(DIc / 16, NCH, 4), 256>>>(F[6], F[7], Bw[6], Bw[7]);

    // 11) out[dir] = y @ out_W -> f32 (8192x384, K=768)
    tc_gemm<<<dim3(3, 64, 2), 256, GEMM_SMEM>>>(yhi, ylo, (long)BLr*DIc,
                                                wohi, wolo, wohi + BNc*DIc, wolo + BNc*DIc,
                                                nullptr, p_do, nullptr, nullptr, (long)BLr*BNc,
                                                BNc, DIc, 0);

    // 12) fused ln + combine -> bf16 hi/lo
    ln_combine<<<BLr, 128>>>(F[9], F[10], Bw[9], Bw[10]);

    // 13) out = comb @ up_W + up_b -> f32 (8192x768, K=384)
    tc_gemm<<<dim3(6, 64, 1), 256, GEMM_SMEM>>>(chi, clo, 0, wuhi, wulo, wuhi, wulo,
                                                up_b, (float*)d_out, nullptr, nullptr, 0,
                                                DIc, BNc, 0);
}

// round 17
// speedup vs baseline: 1.2281x; 1.1904x over previous
#include <cuda_runtime.h>
#include <cuda_bf16.h>
#include <math.h>
#include <stdint.h>

#define Bb   2
#define Ls   4096
#define BLr  (Bb*Ls)          // 8192 rows
#define BNc  384
#define DIc  768
#define NSc  16
#define DCc  4
#define Rc   24
#define XDc  (Rc + 2*NSc)     // 56

#define NCH  16
#define CTs  (Ls/NCH)         // 256
#define TS1  64
#define TS3  16               // p3 segment length (two-phase)
#define DNs  (DIc*NSc)        // 12288

typedef __nv_bfloat16 bf16;

// ---------------- scratch (static device arrays; no allocation) -------------
__device__ float g_xz  [2][BLr*2*DIc];
__device__ float g_xdbl[2][BLr*XDc];
__device__ float g_dt  [2][BLr*DIc];
__device__ float g_do  [2][BLr*BNc];
__device__ float g_aprod[4*NCH*DNs];
__device__ float g_hendl[4*NCH*DNs];
__device__ float g_hin  [4*NCH*DNs];

// bf16 hi/lo activation operands
__device__ bf16 g_xhi[BLr*DIc],  g_xlo[BLr*DIc];
__device__ bf16 g_hhi[BLr*BNc],  g_hlo[BLr*BNc];
__device__ bf16 g_uhi[2][BLr*DIc], g_ulo[2][BLr*DIc];
__device__ bf16 g_yhi[2][BLr*DIc], g_ylo[2][BLr*DIc];
__device__ bf16 g_chi[BLr*BNc],  g_clo[BLr*BNc];

// transposed bf16 hi/lo weights [N,K]
__device__ bf16 g_wdhi[BNc*DIc],      g_wdlo[BNc*DIc];
__device__ bf16 g_wihi[2][2*DIc*BNc], g_wilo[2][2*DIc*BNc];
__device__ bf16 g_wxhi[2][XDc*DIc],   g_wxlo[2][XDc*DIc];
__device__ bf16 g_wohi[2][BNc*DIc],   g_wolo[2][BNc*DIc];
__device__ bf16 g_wuhi[DIc*BNc],      g_wulo[DIc*BNc];

// ---------------- helpers ------------------------------------------------------
__device__ __forceinline__ void split_bf16(float x, bf16& h, bf16& l){
    h = __float2bfloat16_rn(x);
    l = __float2bfloat16_rn(x - __bfloat162float(h));
}
__device__ __forceinline__ void mma16n8k16(float* d, const uint32_t* a, const uint32_t* b){
    asm volatile(
        "mma.sync.aligned.m16n8k16.row.col.f32.bf16.bf16.f32 "
        "{%0,%1,%2,%3}, {%4,%5,%6,%7}, {%8,%9}, {%0,%1,%2,%3};"
        : "+f"(d[0]), "+f"(d[1]), "+f"(d[2]), "+f"(d[3])
        : "r"(a[0]), "r"(a[1]), "r"(a[2]), "r"(a[3]), "r"(b[0]), "r"(b[1]));
}
__device__ __forceinline__ void ldsm4(uint32_t* r, uint32_t addr){
    asm volatile("ldmatrix.sync.aligned.m8n8.x4.shared.b16 {%0,%1,%2,%3}, [%4];"
        : "=r"(r[0]), "=r"(r[1]), "=r"(r[2]), "=r"(r[3]) : "r"(addr));
}
__device__ __forceinline__ void cp16(uint32_t dst, const void* src, int sz){
    asm volatile("cp.async.cg.shared.global [%0], [%1], 16, %2;\n"
                 :: "r"(dst), "l"(src), "r"(sz) : "memory");
}
#define CP_COMMIT() asm volatile("cp.async.commit_group;\n" ::: "memory")
#define CP_WAIT(n)  asm volatile("cp.async.wait_group %0;\n" :: "n"(n) : "memory")

// ---------------- bf16 GEMM, 128x128 tile, KT=64, 3-stage cp.async + LDSM ----
#define ROW_U   36
#define PART_U  (128*ROW_U)        // 4608
#define STAGE_U (4*PART_U)         // 18432
#define GEMM_SMEM (3*STAGE_U*4)    // 221184 bytes

__global__ __launch_bounds__(256, 1) void tc_gemm(
    const bf16* __restrict__ Ahi, const bf16* __restrict__ Alo, long sA,
    const bf16* __restrict__ Whi0, const bf16* __restrict__ Wlo0,
    const bf16* __restrict__ Whi1, const bf16* __restrict__ Wlo1,
    const float* __restrict__ bias,
    float* __restrict__ Cf, bf16* __restrict__ Chi, bf16* __restrict__ Clo, long sC,
    int N, int K, int revz)
{
    extern __shared__ uint32_t sm[];
    const uint32_t smb = (uint32_t)__cvta_generic_to_shared(sm);

    const int z = blockIdx.z;
    const bf16* __restrict__ Whi = z ? Whi1 : Whi0;
    const bf16* __restrict__ Wlo = z ? Wlo1 : Wlo0;
    Ahi += (long)z * sA;  Alo += (long)z * sA;
    if (Cf)  Cf  += (long)z * sC;
    if (Chi) { Chi += (long)z * sC; Clo += (long)z * sC; }

    const int tid  = threadIdx.x;
    const int lane = tid & 31;
    const int wid  = tid >> 5;
    const int warpM = wid & 3;
    const int warpN = wid >> 2;
    const int gid = lane >> 2;
    const int tig = lane & 3;

    const int crow = blockIdx.y * 128;
    const int ccol = blockIdx.x * 128;

    const uint32_t aOff = (uint32_t)((warpM * 32 + (lane & 15)) * 144 + (lane >> 4) * 16);
    const uint32_t bOff = (uint32_t)((warpN * 64 + (lane & 7) + ((lane >> 4) << 3)) * 144
                                     + ((lane >> 3) & 1) * 16);

    const int segA = tid & 7;
    const long dAlo = Alo - Ahi;
    const long dWlo = Wlo - Whi;
    const bf16* aP[4]; const bf16* bP[4];
    uint32_t dAb[4], dBb[4]; int szB[4];
#pragma unroll
    for (int j = 0; j < 4; j++) {
        const int row = (tid >> 3) + 32 * j;
        int gRow = crow + row;
        if (revz && z == 1) {
            int bb = gRow / Ls, t = gRow - bb * Ls;
            gRow = bb * Ls + (Ls - 1 - t);
        }
        aP[j] = Ahi + (long)gRow * K + segA * 8;
        dAb[j] = smb + (uint32_t)(row * ROW_U + segA * 4) * 4u;
        const int ng = ccol + row;
        bP[j] = Whi + (long)ng * K + segA * 8;
        szB[j] = (ng < N) ? 16 : 0;
        dBb[j] = smb + (uint32_t)(2 * PART_U + row * ROW_U + segA * 4) * 4u;
    }

#define ISSUE(KT, S)                                                           \
    {                                                                          \
        const uint32_t so = (uint32_t)(S) * STAGE_U * 4u;                      \
        const int ko = (KT) * 64;                                              \
        _Pragma("unroll")                                                      \
        for (int j = 0; j < 4; j++) {                                          \
            cp16(dAb[j] + so,               aP[j] + ko,        16);            \
            cp16(dAb[j] + so + PART_U * 4u, aP[j] + dAlo + ko, 16);            \
            cp16(dBb[j] + so,               bP[j] + ko,        szB[j]);        \
            cp16(dBb[j] + so + PART_U * 4u, bP[j] + dWlo + ko, szB[j]);        \
        }                                                                      \
        CP_COMMIT();                                                           \
    }

    float acc[2][8][4];
#pragma unroll
    for (int m = 0; m < 2; m++)
#pragma unroll
        for (int n = 0; n < 8; n++)
#pragma unroll
            for (int q = 0; q < 4; q++) acc[m][n][q] = 0.f;

    const int nkt = K >> 6;

    ISSUE(0, 0);
    if (nkt > 1) ISSUE(1, 1);

    int s = 0;
    for (int kt = 0; kt < nkt; kt++) {
        if (kt + 1 < nkt) { CP_WAIT(1); }
        else              { CP_WAIT(0); }
        __syncthreads();

        const uint32_t stg = smb + (uint32_t)s * STAGE_U * 4u;
        const uint32_t aHi = stg + aOff;
        const uint32_t aLo = aHi + PART_U * 4u;
        const uint32_t bHi = stg + 2u * PART_U * 4u + bOff;
        const uint32_t bLo = bHi + PART_U * 4u;

#pragma unroll
        for (int ks = 0; ks < 4; ks++) {
            const uint32_t ko = (uint32_t)ks * 32u;
            uint32_t ah[2][4], al[2][4];
            uint32_t bh[4][4], bl[4][4];
#pragma unroll
            for (int m = 0; m < 2; m++) {
                ldsm4(ah[m], aHi + m * 2304u + ko);
                ldsm4(al[m], aLo + m * 2304u + ko);
            }
#pragma unroll
            for (int g2 = 0; g2 < 4; g2++) {
                ldsm4(bh[g2], bHi + g2 * 2304u + ko);
                ldsm4(bl[g2], bLo + g2 * 2304u + ko);
            }
#pragma unroll
            for (int g2 = 0; g2 < 4; g2++)
#pragma unroll
                for (int sub = 0; sub < 2; sub++)
#pragma unroll
                    for (int m = 0; m < 2; m++)
                        mma16n8k16(acc[m][g2*2+sub], ah[m], &bh[g2][sub*2]);
#pragma unroll
            for (int g2 = 0; g2 < 4; g2++)
#pragma unroll
                for (int sub = 0; sub < 2; sub++)
#pragma unroll
                    for (int m = 0; m < 2; m++)
                        mma16n8k16(acc[m][g2*2+sub], ah[m], &bl[g2][sub*2]);
#pragma unroll
            for (int g2 = 0; g2 < 4; g2++)
#pragma unroll
                for (int sub = 0; sub < 2; sub++)
#pragma unroll
                    for (int m = 0; m < 2; m++)
                        mma16n8k16(acc[m][g2*2+sub], al[m], &bh[g2][sub*2]);
        }

        if (kt + 2 < nkt) {
            const int s2 = (s + 2 >= 3) ? s - 1 : s + 2;
            ISSUE(kt + 2, s2);
        }
        s = (s + 1 == 3) ? 0 : s + 1;
    }

    // epilogue
#pragma unroll
    for (int m = 0; m < 2; m++) {
        const int r0 = crow + warpM * 32 + m * 16 + gid;
#pragma unroll
        for (int n = 0; n < 8; n++) {
            const int c = ccol + warpN * 64 + n * 8 + tig * 2;
            if (c < N) {
                float2 v0 = make_float2(acc[m][n][0], acc[m][n][1]);
                float2 v1 = make_float2(acc[m][n][2], acc[m][n][3]);
                if (bias) {
                    const float b0 = bias[c], b1 = bias[c + 1];
                    v0.x += b0; v0.y += b1; v1.x += b0; v1.y += b1;
                }
                if (Cf) {
                    *(float2*)&Cf[(long)r0 * N + c]       = v0;
                    *(float2*)&Cf[(long)(r0 + 8) * N + c] = v1;
                } else {
                    bf16 h0,l0,h1,l1;
                    split_bf16(v0.x, h0, l0); split_bf16(v0.y, h1, l1);
                    *(__nv_bfloat162*)&Chi[(long)r0 * N + c] = __nv_bfloat162(h0, h1);
                    *(__nv_bfloat162*)&Clo[(long)r0 * N + c] = __nv_bfloat162(l0, l1);
                    split_bf16(v1.x, h0, l0); split_bf16(v1.y, h1, l1);
                    *(__nv_bfloat162*)&Chi[(long)(r0 + 8) * N + c] = __nv_bfloat162(h0, h1);
                    *(__nv_bfloat162*)&Clo[(long)(r0 + 8) * N + c] = __nv_bfloat162(l0, l1);
                }
            }
        }
    }
#undef ISSUE
}

// ---------------- pre-split passes -------------------------------------------
__global__ void split_pass(const float* __restrict__ src, bf16* __restrict__ hi,
                           bf16* __restrict__ lo, long n)
{
    long i = (long)blockIdx.x * blockDim.x + threadIdx.x;
    if (i >= n) return;
    bf16 h, l; split_bf16(src[i], h, l);
    hi[i] = h; lo[i] = l;
}

struct SplitJobs {
    const float* src[8];
    bf16* hi[8];
    bf16* lo[8];
    int K[8];
    int N[8];
};
__global__ void wsplit_all(SplitJobs J)
{
    const int j = blockIdx.y;
    const int K = J.K[j], N = J.N[j];
    long i = (long)blockIdx.x * blockDim.x + threadIdx.x;
    if (i >= (long)N * K) return;
    int n = (int)(i / K), k = (int)(i % K);
    bf16 h, l; split_bf16(J.src[j][(long)k * N + n], h, l);
    J.hi[j][i] = h; J.lo[j][i] = l;
}

// ---------------- causal depthwise conv (DC=4) + SiLU -> bf16 hi/lo ----------
__global__ void conv_silu(const float* __restrict__ cw0, const float* __restrict__ cb0,
                          const float* __restrict__ cw1, const float* __restrict__ cb1)
{
    const int dir = blockIdx.y;
    long idx = (long)blockIdx.x * blockDim.x + threadIdx.x;
    if (idx >= (long)BLr * DIc) return;
    const int d = (int)(idx % DIc);
    const long row = idx / DIc;
    const int t = (int)(row % Ls);
    const float* cw = dir ? cw1 : cw0;
    const float* cb = dir ? cb1 : cb0;
    const float* xs = g_xz[dir];

    float s = cb[d];
#pragma unroll
    for (int k = 0; k < DCc; k++) {
        int tt = t - (DCc - 1) + k;
        if (tt >= 0) s += xs[(row - t + tt) * (2 * DIc) + d] * cw[d * DCc + k];
    }
    float sig = 1.f / (1.f + __expf(-s));
    float v = s * sig;
    bf16 h, l; split_bf16(v, h, l);
    g_uhi[dir][idx] = h; g_ulo[dir][idx] = l;
}

// ---------------- dt = softplus(dt_raw @ dt_W + dt_b) ------------------------
__global__ __launch_bounds__(256) void dt_kernel(
    const float* __restrict__ W0, const float* __restrict__ b0,
    const float* __restrict__ W1, const float* __restrict__ b1)
{
    const int dir = blockIdx.y;
    const int row0 = blockIdx.x * 16;
    const int tid = threadIdx.x;
    __shared__ float xd[16][Rc];
    for (int i = tid; i < 16 * Rc; i += 256) {
        int r = i / Rc, c = i - r * Rc;
        xd[r][c] = g_xdbl[dir][(long)(row0 + r) * XDc + c];
    }
    __syncthreads();
    const float* W  = dir ? W1 : W0;
    const float* bb = dir ? b1 : b0;
    for (int d = tid; d < DIc; d += 256) {
        float w[Rc];
#pragma unroll
        for (int r = 0; r < Rc; r++) w[r] = W[r * DIc + d];
        const float bias = bb[d];
#pragma unroll 4
        for (int rr = 0; rr < 16; rr++) {
            float s = bias;
#pragma unroll
            for (int r = 0; r < Rc; r++) s += xd[rr][r] * w[r];
            float sp = fmaxf(s, 0.f) + log1pf(__expf(-fabsf(s)));
            g_dt[dir][(long)(row0 + rr) * DIc + d] = sp;
        }
    }
}

// ---------------- chunked selective scan --------------------------------------
__global__ __launch_bounds__(256) void scan_p1(
    const float* __restrict__ Alog0, const float* __restrict__ Alog1)
{
    const int dir = blockIdx.z >> 1, b = blockIdx.z & 1;
    const int chunk = blockIdx.y;
    const int d0 = blockIdx.x * 16;
    const int tid = threadIdx.x, n = tid & 15, dd = tid >> 4;
    const float* Alog = dir ? Alog1 : Alog0;
    const float Ac = -expf(Alog[(d0 + dd) * NSc + n]);

    const long row0 = (long)b * Ls + (long)chunk * CTs;
    const float* dt_p = g_dt[dir]   + row0 * DIc + d0;
    const bf16*  uh_p = g_uhi[dir]  + row0 * DIc + d0;
    const bf16*  ul_p = g_ulo[dir]  + row0 * DIc + d0;
    const float* xd_p = g_xdbl[dir] + row0 * XDc;

    __shared__ float s_dt[2][TS1][16], s_u[2][TS1][16], s_B[2][TS1][16];

    float r0[4], r1[4], r2[4];
#define P1_LDG(SEG)                                                            \
    {                                                                          \
        _Pragma("unroll")                                                      \
        for (int j = 0; j < 4; j++) {                                          \
            const int ix = tid + j * 256;                                      \
            const int t = ix >> 4, c = ix & 15;                                \
            const long tt = (long)((SEG) * TS1 + t);                           \
            r0[j] = dt_p[tt * DIc + c];                                        \
            r1[j] = __bfloat162float(uh_p[tt * DIc + c])                       \
                  + __bfloat162float(ul_p[tt * DIc + c]);                      \
            r2[j] = xd_p[tt * XDc + Rc + c];                                   \
        }                                                                      \
    }
#define P1_STS(BUF)                                                            \
    {                                                                          \
        _Pragma("unroll")                                                      \
        for (int j = 0; j < 4; j++) {                                          \
            const int ix = tid + j * 256;                                      \
            const int t = ix >> 4, c = ix & 15;                                \
            s_dt[BUF][t][c] = r0[j];                                           \
            s_u [BUF][t][c] = r1[j];                                           \
            s_B [BUF][t][c] = r2[j];                                           \
        }                                                                      \
    }

    P1_LDG(0); P1_STS(0); __syncthreads();

    float h = 0.f, ap = 1.f;
    for (int seg = 0; seg < CTs / TS1; seg++) {
        const int buf = seg & 1;
        const bool more = (seg + 1) < (CTs / TS1);
        if (more) P1_LDG(seg + 1);
#pragma unroll 8
        for (int t = 0; t < TS1; t++) {
            const float dtv = s_dt[buf][t][dd];
            const float uv  = s_u [buf][t][dd];
            const float Bv  = s_B [buf][t][n];
            const float dA  = __expf(dtv * Ac);
            h = dA * h + dtv * uv * Bv;
            ap *= dA;
        }
        if (more) P1_STS(buf ^ 1);
        __syncthreads();
    }

    const long so = ((long)(dir * Bb + b) * NCH + chunk) * DNs + (long)(d0 + dd) * NSc + n;
    g_aprod[so] = ap;
    g_hendl[so] = h;
#undef P1_LDG
#undef P1_STS
}

__global__ void scan_p2()
{
    const int idx = blockIdx.x * 256 + threadIdx.x;
    if (idx >= 4 * DNs) return;
    const int zb = idx / DNs, dn = idx % DNs;
    const long base = (long)zb * NCH * DNs + dn;
    float hin = 0.f;
#pragma unroll
    for (int c = 0; c < NCH; c++) {
        const long o = base + (long)c * DNs;
        g_hin[o] = hin;
        hin = g_aprod[o] * hin + g_hendl[o];
    }
}

// Phase-split p3: no shuffles. Phase A does the recurrence and stores h*C to
// smem; Phase B reduces 16 states per (t,d), gates, writes bf16 hi/lo.
__global__ __launch_bounds__(256) void scan_p3(
    const float* __restrict__ Alog0, const float* __restrict__ D0,
    const float* __restrict__ Alog1, const float* __restrict__ D1)
{
    const int dir = blockIdx.z >> 1, b = blockIdx.z & 1;
    const int chunk = blockIdx.y;
    const int d0 = blockIdx.x * 16;
    const int tid = threadIdx.x, n = tid & 15, dd = tid >> 4;
    const float* Alog = dir ? Alog1 : Alog0;
    const float Ac = -expf(Alog[(d0 + dd) * NSc + n]);
    // Phase-B identity: thread -> (tB, dB)
    const int tB = tid >> 4, dB = tid & 15;
    const float DvB = (dir ? D1 : D0)[d0 + dB];

    const long row0 = (long)b * Ls + (long)chunk * CTs;
    const float* dt_p = g_dt[dir]   + row0 * DIc + d0;
    const bf16*  uh_p = g_uhi[dir]  + row0 * DIc + d0;
    const bf16*  ul_p = g_ulo[dir]  + row0 * DIc + d0;
    const float* xd_p = g_xdbl[dir] + row0 * XDc;
    const float* z_p  = g_xz[dir]   + row0 * (2 * DIc) + DIc + d0;
    bf16* yhi_p = g_yhi[dir] + row0 * DIc + d0;
    bf16* ylo_p = g_ylo[dir] + row0 * DIc + d0;

    __shared__ float s_dt[2][TS3][16], s_u[2][TS3][16], s_B[2][TS3][16],
                     s_C[2][TS3][16], s_z[2][TS3][16];
    __shared__ float s_hc[TS3][16][17];     // [t][d][n] padded

    float r0, r1, r2, r3, r4;
#define P3_LDG(SEG)                                                            \
    {                                                                          \
        const int t = tid >> 4, c = tid & 15;                                  \
        const long tt = (long)((SEG) * TS3 + t);                               \
        r0 = dt_p[tt * DIc + c];                                               \
        r1 = __bfloat162float(uh_p[tt * DIc + c])                              \
           + __bfloat162float(ul_p[tt * DIc + c]);                             \
        r2 = xd_p[tt * XDc + Rc + c];                                          \
        r3 = xd_p[tt * XDc + Rc + NSc + c];                                    \
        r4 = z_p [tt * 2 * DIc + c];                                           \
    }
#define P3_STS(BUF)                                                            \
    {                                                                          \
        const int t = tid >> 4, c = tid & 15;                                  \
        s_dt[BUF][t][c] = r0;                                                  \
        s_u [BUF][t][c] = r1;                                                  \
        s_B [BUF][t][c] = r2;                                                  \
        s_C [BUF][t][c] = r3;                                                  \
        s_z [BUF][t][c] = r4;                                                  \
    }

    P3_LDG(0); P3_STS(0); __syncthreads();

    const long so = ((long)(dir * Bb + b) * NCH + chunk) * DNs + (long)(d0 + dd) * NSc + n;
    float h = g_hin[so];

    for (int seg = 0; seg < CTs / TS3; seg++) {
        const int buf = seg & 1;
        const bool more = (seg + 1) < (CTs / TS3);
        if (more) P3_LDG(seg + 1);

        // Phase A: recurrence, store h*C
#pragma unroll
        for (int t = 0; t < TS3; t++) {
            const float dtv = s_dt[buf][t][dd];
            const float uv  = s_u [buf][t][dd];
            const float Bv  = s_B [buf][t][n];
            const float Cv  = s_C [buf][t][n];
            const float dA  = __expf(dtv * Ac);
            h = dA * h + dtv * uv * Bv;
            s_hc[t][dd][n] = h * Cv;
        }
        __syncthreads();

        // Phase B: each thread owns (tB, dB)
        {
            float y = 0.f;
#pragma unroll
            for (int q = 0; q < 16; q++) y += s_hc[tB][dB][q];
            const float uv = s_u[buf][tB][dB];
            const float zv = s_z[buf][tB][dB];
            const float sig = 1.f / (1.f + __expf(-zv));
            const float v = (y + uv * DvB) * (zv * sig);
            bf16 hh, ll; split_bf16(v, hh, ll);
            const long o = (long)(seg * TS3 + tB) * DIc + dB;
            yhi_p[o] = hh; ylo_p[o] = ll;
        }

        if (more) P3_STS(buf ^ 1);
        __syncthreads();
    }
#undef P3_LDG
#undef P3_STS
}

// ---------------- fused LayerNorm(fwd) + LayerNorm(bwd,rev) + add -> bf16 ----
__global__ void ln_combine(const float* __restrict__ g0, const float* __restrict__ b0,
                           const float* __restrict__ g1, const float* __restrict__ b1)
{
    const int row = blockIdx.x;
    const int b = row / Ls, t = row % Ls;
    const float* pf = g_do[0] + (long)row * BNc;
    const float* pb = g_do[1] + ((long)b * Ls + (Ls - 1 - t)) * BNc;
    __shared__ float2 red[128];
    const int tid = threadIdx.x;

    float vf[3], vb[3];
    float sf = 0.f, sb = 0.f;
#pragma unroll
    for (int i = 0; i < 3; i++) {
        vf[i] = pf[tid + i * 128]; sf += vf[i];
        vb[i] = pb[tid + i * 128]; sb += vb[i];
    }
    red[tid] = make_float2(sf, sb); __syncthreads();
    for (int st = 64; st > 0; st >>= 1) {
        if (tid < st) { red[tid].x += red[tid + st].x; red[tid].y += red[tid + st].y; }
        __syncthreads();
    }
    const float mf = red[0].x / (float)BNc;
    const float mb = red[0].y / (float)BNc;
    __syncthreads();

    float qf = 0.f, qb = 0.f;
#pragma unroll
    for (int i = 0; i < 3; i++) {
        float df = vf[i] - mf; qf += df * df;
        float db = vb[i] - mb; qb += db * db;
    }
    red[tid] = make_float2(qf, qb); __syncthreads();
    for (int st = 64; st > 0; st >>= 1) {
        if (tid < st) { red[tid].x += red[tid + st].x; red[tid].y += red[tid + st].y; }
        __syncthreads();
    }
    const float rf = rsqrtf(red[0].x / (float)BNc + 1e-5f);
    const float rb = rsqrtf(red[0].y / (float)BNc + 1e-5f);

#pragma unroll
    for (int i = 0; i < 3; i++) {
        const int c = tid + i * 128;
        const float v = (vf[i] - mf) * rf * g0[c] + b0[c]
                      + (vb[i] - mb) * rb * g1[c] + b1[c];
        bf16 h, l; split_bf16(v, h, l);
        g_chi[(long)row * BNc + c] = h;
        g_clo[(long)row * BNc + c] = l;
    }
}

// ------------------------------------------------------------------------------
extern "C" void kernel_launch(void* const* d_in, const int* in_sizes, int n_in,
                              void* d_out, int out_size)
{
    (void)in_sizes; (void)n_in; (void)out_size;
    const float* x      = (const float*)d_in[0];
    const float* down_W = (const float*)d_in[1];
    const float* down_b = (const float*)d_in[2];
    const float* up_W   = (const float*)d_in[3];
    const float* up_b   = (const float*)d_in[4];
    const float* F[11]; const float* Bw[11];
    for (int i = 0; i < 11; i++) { F[i] = (const float*)d_in[5 + i]; Bw[i] = (const float*)d_in[16 + i]; }

    float *p_xz, *p_xdbl, *p_do;
    cudaGetSymbolAddress((void**)&p_xz,   g_xz);
    cudaGetSymbolAddress((void**)&p_xdbl, g_xdbl);
    cudaGetSymbolAddress((void**)&p_do,   g_do);
    bf16 *xhi,*xlo,*hhi,*hlo,*uhi,*ulo,*yhi,*ylo,*chi,*clo;
    cudaGetSymbolAddress((void**)&xhi, g_xhi); cudaGetSymbolAddress((void**)&xlo, g_xlo);
    cudaGetSymbolAddress((void**)&hhi, g_hhi); cudaGetSymbolAddress((void**)&hlo, g_hlo);
    cudaGetSymbolAddress((void**)&uhi, g_uhi); cudaGetSymbolAddress((void**)&ulo, g_ulo);
    cudaGetSymbolAddress((void**)&yhi, g_yhi); cudaGetSymbolAddress((void**)&ylo, g_ylo);
    cudaGetSymbolAddress((void**)&chi, g_chi); cudaGetSymbolAddress((void**)&clo, g_clo);
    bf16 *wdhi,*wdlo,*wihi,*wilo,*wxhi,*wxlo,*wohi,*wolo,*wuhi,*wulo;
    cudaGetSymbolAddress((void**)&wdhi, g_wdhi); cudaGetSymbolAddress((void**)&wdlo, g_wdlo);
    cudaGetSymbolAddress((void**)&wihi, g_wihi); cudaGetSymbolAddress((void**)&wilo, g_wilo);
    cudaGetSymbolAddress((void**)&wxhi, g_wxhi); cudaGetSymbolAddress((void**)&wxlo, g_wxlo);
    cudaGetSymbolAddress((void**)&wohi, g_wohi); cudaGetSymbolAddress((void**)&wolo, g_wolo);
    cudaGetSymbolAddress((void**)&wuhi, g_wuhi); cudaGetSymbolAddress((void**)&wulo, g_wulo);

    cudaFuncSetAttribute(tc_gemm, cudaFuncAttributeMaxDynamicSharedMemorySize, GEMM_SMEM);

    // 1) input split
    split_pass<<<(BLr*DIc + 255)/256, 256>>>(x, xhi, xlo, (long)BLr*DIc);

    // 2) ALL weight splits in one launch
    SplitJobs J;
    J.src[0] = down_W; J.hi[0] = wdhi;             J.lo[0] = wdlo;             J.K[0] = DIc; J.N[0] = BNc;
    J.src[1] = F[0];   J.hi[1] = wihi;             J.lo[1] = wilo;             J.K[1] = BNc; J.N[1] = 2*DIc;
    J.src[2] = Bw[0];  J.hi[2] = wihi + 2*DIc*BNc; J.lo[2] = wilo + 2*DIc*BNc; J.K[2] = BNc; J.N[2] = 2*DIc;
    J.src[3] = F[3];   J.hi[3] = wxhi;             J.lo[3] = wxlo;             J.K[3] = DIc; J.N[3] = XDc;
    J.src[4] = Bw[3];  J.hi[4] = wxhi + XDc*DIc;   J.lo[4] = wxlo + XDc*DIc;   J.K[4] = DIc; J.N[4] = XDc;
    J.src[5] = F[8];   J.hi[5] = wohi;             J.lo[5] = wolo;             J.K[5] = DIc; J.N[5] = BNc;
    J.src[6] = Bw[8];  J.hi[6] = wohi + BNc*DIc;   J.lo[6] = wolo + BNc*DIc;   J.K[6] = DIc; J.N[6] = BNc;
    J.src[7] = up_W;   J.hi[7] = wuhi;             J.lo[7] = wulo;             J.K[7] = BNc; J.N[7] = DIc;
    wsplit_all<<<dim3((2*DIc*BNc + 255)/256, 8), 256>>>(J);

    // 3) down GEMM
    tc_gemm<<<dim3(3, 64, 1), 256, GEMM_SMEM>>>(xhi, xlo, 0, wdhi, wdlo, wdhi, wdlo,
                                                down_b, nullptr, hhi, hlo, 0,
                                                BNc, DIc, 0);

    // 4) in GEMM
    tc_gemm<<<dim3(12, 64, 2), 256, GEMM_SMEM>>>(hhi, hlo, 0,
                                                 wihi, wilo, wihi + 2*DIc*BNc, wilo + 2*DIc*BNc,
                                                 nullptr, p_xz, nullptr, nullptr, (long)BLr*2*DIc,
                                                 2*DIc, BNc, 1);

    // 5) conv
    conv_silu<<<dim3((BLr * DIc + 255) / 256, 2), 256>>>(F[1], F[2], Bw[1], Bw[2]);

    // 6) xproj GEMM
    tc_gemm<<<dim3(1, 64, 2), 256, GEMM_SMEM>>>(uhi, ulo, (long)BLr*DIc,
                                                wxhi, wxlo, wxhi + XDc*DIc, wxlo + XDc*DIc,
                                                nullptr, p_xdbl, nullptr, nullptr, (long)BLr*XDc,
                                                XDc, DIc, 0);

    // 7) dt
    dt_kernel<<<dim3(BLr / 16, 2), 256>>>(F[4], F[5], Bw[4], Bw[5]);

    // 8-10) chunked scan
    scan_p1<<<dim3(DIc / 16, NCH, 4), 256>>>(F[6], Bw[6]);
    scan_p2<<<(4 * DNs + 255) / 256, 256>>>();
    scan_p3<<<dim3(DIc / 16, NCH, 4), 256>>>(F[6], F[7], Bw[6], Bw[7]);

    // 11) out GEMM
    tc_gemm<<<dim3(3, 64, 2), 256, GEMM_SMEM>>>(yhi, ylo, (long)BLr*DIc,
                                                wohi, wolo, wohi + BNc*DIc, wolo + BNc*DIc,
                                                nullptr, p_do, nullptr, nullptr, (long)BLr*BNc,
                                                BNc, DIc, 0);

    // 12) fused ln + combine
    ln_combine<<<BLr, 128>>>(F[9], F[10], Bw[9], Bw[10]);

    // 13) up GEMM
    tc_gemm<<<dim3(6, 64, 1), 256, GEMM_SMEM>>>(chi, clo, 0, wuhi, wulo, wuhi, wulo,
                                                up_b, (float*)d_out, nullptr, nullptr, 0,
                                                DIc, BNc, 0);
}